// round 1
// baseline (speedup 1.0000x reference)
#include <cuda_runtime.h>
#include <cuda_fp16.h>
#include <mma.h>

using namespace nvcuda;

// Problem dims (fixed by the reference)
#define BATCH   4
#define NHEAD   8
#define DH      128     // per-head channel dim (and dv)
#define TT      2048    // sequence length (Tq = Tk)
#define ALPHA   5.0f

#define QT      64      // query tile
#define KT      64      // key tile
#define NTHREADS 256

// smem leading dims (halves must be multiple of 8, floats multiple of 4)
#define LDQ   72
#define LDK   72
#define LDV   72
#define LDPF  68
#define LDPH  72
#define LDO   132

// smem byte offsets
#define OFF_QS    0
#define OFF_KS    18432                 // 128*72*2
#define OFF_VS    36864
#define OFF_PSF   55296                 // 64*68*4 = 17408
#define OFF_PSH   72704                 // 64*72*2 = 9216
#define OFF_L     81920                 // 64*4
#define OFF_PART  82176                 // 256*4
#define SMEM_BYTES 83200

__global__ __launch_bounds__(NTHREADS, 2)
void attn_cosine_kernel(const float* __restrict__ q,
                        const float* __restrict__ k,
                        const float* __restrict__ v,
                        float* __restrict__ out)
{
    extern __shared__ char smem[];
    half*  Qs   = (half*)(smem + OFF_QS);
    half*  Ks   = (half*)(smem + OFF_KS);
    half*  Vs   = (half*)(smem + OFF_VS);
    float* Psf  = (float*)(smem + OFF_PSF);
    half*  Psh  = (half*)(smem + OFF_PSH);
    float* lsum = (float*)(smem + OFF_L);
    float* part = (float*)(smem + OFF_PART);
    float* Os   = (float*)(smem + OFF_QS);   // reused at the very end (33792 B < Qs+Ks)

    const int qtile = blockIdx.x;            // 0..31
    const int bh    = blockIdx.y;            // 0..31
    const int tid   = threadIdx.x;
    const int t     = tid & 63;              // time index within tile
    const int g     = tid >> 6;              // channel group 0..3
    const int wid   = tid >> 5;
    const int wr    = wid >> 1;              // warp row 0..3 (16 queries each)
    const int wc    = wid & 1;               // warp col 0..1

    const float* qbase = q + (size_t)bh * DH * TT + (size_t)qtile * QT;
    const float* kbase = k + (size_t)bh * DH * TT;
    const float* vbase = v + (size_t)bh * DH * TT;

    if (tid < QT) lsum[tid] = 0.0f;

    // ---- load + l2-normalize Q tile into Qs[c][t] (fp16) ----
    {
        float vals[32];
        float ss = 0.0f;
        #pragma unroll
        for (int i = 0; i < 32; i++) {
            int c = g * 32 + i;
            float x = qbase[(size_t)c * TT + t];
            vals[i] = x;
            ss += x * x;
        }
        part[tid] = ss;
        __syncthreads();
        if (tid < 64) {
            float s = part[tid] + part[tid + 64] + part[tid + 128] + part[tid + 192];
            part[tid] = 1.0f / fmaxf(sqrtf(s), 1e-12f);
        }
        __syncthreads();
        float inv = part[t];
        #pragma unroll
        for (int i = 0; i < 32; i++) {
            int c = g * 32 + i;
            Qs[c * LDQ + t] = __float2half(vals[i] * inv);
        }
    }

    // persistent output accumulators: 16 q-rows x 64 dv-cols per warp
    wmma::fragment<wmma::accumulator, 16, 16, 16, float> o_acc[4];
    #pragma unroll
    for (int j = 0; j < 4; j++) wmma::fill_fragment(o_acc[j], 0.0f);

    for (int kt0 = 0; kt0 < TT; kt0 += KT) {
        __syncthreads();   // previous iteration's consumers of Ks/Vs/Psh/part done

        // ---- load + normalize K tile into Ks[c][kt] ----
        {
            const float* kp = kbase + kt0;
            float vals[32];
            float ss = 0.0f;
            #pragma unroll
            for (int i = 0; i < 32; i++) {
                int c = g * 32 + i;
                float x = kp[(size_t)c * TT + t];
                vals[i] = x;
                ss += x * x;
            }
            part[tid] = ss;
            __syncthreads();
            if (tid < 64) {
                float s = part[tid] + part[tid + 64] + part[tid + 128] + part[tid + 192];
                part[tid] = 1.0f / fmaxf(sqrtf(s), 1e-12f);
            }
            __syncthreads();
            float inv = part[t];
            #pragma unroll
            for (int i = 0; i < 32; i++) {
                int c = g * 32 + i;
                Ks[c * LDK + t] = __float2half(vals[i] * inv);
            }
        }

        // ---- load V tile into Vs[dv][kt] (direct copy, no transpose) ----
        {
            const float* vp = vbase + kt0;
            #pragma unroll
            for (int i = 0; i < 32; i++) {
                int dr = g * 32 + i;
                Vs[dr * LDV + t] = __float2half(vp[(size_t)dr * TT + t]);
            }
        }
        __syncthreads();

        // ---- S = Qn^T * Kn : each warp 16 q-rows x 32 k-cols ----
        wmma::fragment<wmma::accumulator, 16, 16, 16, float> sacc[2];
        wmma::fill_fragment(sacc[0], 0.0f);
        wmma::fill_fragment(sacc[1], 0.0f);
        #pragma unroll
        for (int kk = 0; kk < DH; kk += 16) {
            wmma::fragment<wmma::matrix_a, 16, 16, 16, half, wmma::col_major> af;
            wmma::load_matrix_sync(af, Qs + kk * LDQ + wr * 16, LDQ);
            #pragma unroll
            for (int j = 0; j < 2; j++) {
                wmma::fragment<wmma::matrix_b, 16, 16, 16, half, wmma::row_major> bf;
                wmma::load_matrix_sync(bf, Ks + kk * LDK + wc * 32 + j * 16, LDK);
                wmma::mma_sync(sacc[j], af, bf, sacc[j]);
            }
        }

        // ---- P = exp(alpha * S) : elementwise on fragment (layout-agnostic) ----
        #pragma unroll
        for (int j = 0; j < 2; j++) {
            #pragma unroll
            for (int e = 0; e < sacc[j].num_elements; e++)
                sacc[j].x[e] = __expf(ALPHA * sacc[j].x[e]);
            wmma::store_matrix_sync(Psf + (wr * 16) * LDPF + wc * 32 + j * 16,
                                    sacc[j], LDPF, wmma::mem_row_major);
        }
        __syncthreads();

        // ---- convert P -> fp16 + partial rowsums ----
        {
            int qrow = tid >> 2;
            int ch   = tid & 3;
            float s = 0.0f;
            #pragma unroll
            for (int j = 0; j < 16; j++) {
                float pv = Psf[qrow * LDPF + ch * 16 + j];
                Psh[qrow * LDPH + ch * 16 + j] = __float2half(pv);
                s += pv;
            }
            part[tid] = s;
        }
        __syncthreads();
        if (tid < QT)
            lsum[tid] += part[tid * 4] + part[tid * 4 + 1] + part[tid * 4 + 2] + part[tid * 4 + 3];

        // ---- O += P * V : each warp 16 q-rows x 64 dv-cols ----
        #pragma unroll
        for (int kk = 0; kk < KT; kk += 16) {
            wmma::fragment<wmma::matrix_a, 16, 16, 16, half, wmma::row_major> af2;
            wmma::load_matrix_sync(af2, Psh + (wr * 16) * LDPH + kk, LDPH);
            #pragma unroll
            for (int j = 0; j < 4; j++) {
                wmma::fragment<wmma::matrix_b, 16, 16, 16, half, wmma::col_major> bf2;
                wmma::load_matrix_sync(bf2, Vs + (wc * 64 + j * 16) * LDV + kk, LDV);
                wmma::mma_sync(o_acc[j], af2, bf2, o_acc[j]);
            }
        }
    }

    __syncthreads();   // all mma reads of Qs/Ks done before Os overwrite
    #pragma unroll
    for (int j = 0; j < 4; j++)
        wmma::store_matrix_sync(Os + (wr * 16) * LDO + wc * 64 + j * 16,
                                o_acc[j], LDO, wmma::mem_row_major);
    __syncthreads();

    // ---- write out[b, h*128+dv, qtile*64+t] = Os[t][dv] / lsum[t] ----
    {
        float* obase = out + (size_t)bh * DH * TT + (size_t)qtile * QT;
        float invl = 1.0f / lsum[t];
        #pragma unroll
        for (int i = 0; i < 32; i++) {
            int dr = g * 32 + i;
            obase[(size_t)dr * TT + t] = Os[t * LDO + dr] * invl;
        }
    }
}

extern "C" void kernel_launch(void* const* d_in, const int* in_sizes, int n_in,
                              void* d_out, int out_size)
{
    const float* q = (const float*)d_in[0];
    const float* k = (const float*)d_in[1];
    const float* v = (const float*)d_in[2];
    float* out = (float*)d_out;

    cudaFuncSetAttribute(attn_cosine_kernel,
                         cudaFuncAttributeMaxDynamicSharedMemorySize, SMEM_BYTES);

    dim3 grid(TT / QT, BATCH * NHEAD);   // qtile fastest -> K/V reuse in L2
    attn_cosine_kernel<<<grid, NTHREADS, SMEM_BYTES>>>(q, k, v, out);
}

// round 3
// speedup vs baseline: 2.0381x; 2.0381x over previous
#include <cuda_runtime.h>
#include <cuda_fp16.h>
#include <cstdint>

// ---------------- problem constants ----------------
#define BATCH 4
#define NHEAD 8
#define NBH   32
#define DH    128           // per-head channels (= dv)
#define TT    2048
#define ALPHA 5.0f
#define QT    128           // queries per CTA (8 warps x 16 rows)
#define KT    64            // key tile
#define NITER (TT / KT)     // 32

// ---------------- scratch: pre-normalized fp16 operands ----------------
__device__ __half g_QT[(size_t)NBH * TT * DH];  // [bh][t][ch]  (A row-major)
__device__ __half g_KT[(size_t)NBH * TT * DH];  // [bh][t][ch]  (B "col" = n-major rows)
__device__ __half g_VB[(size_t)NBH * DH * TT];  // [bh][dv][t]  (B n-major rows for PV)

// ---------------- smem layout (bytes) ----------------
// lsum[128] floats at 0; buffers from 512
#define OFF_LS   0
#define OFF_K0   512
#define OFF_V0   17920         // 512 + 64*272
#define OFF_K1   36352         // + 128*144
#define OFF_V1   53760
#define SMEM_BYTES 72192
#define LDKB 272               // K row stride bytes (136 halves)
#define LDVB 144               // V row stride bytes (72 halves)
#define LDO  130               // O staging stride (floats)
// Q staging aliases OFF_K0.. (34816 B), O staging aliases OFF_K0.. (66560 B)

__device__ __forceinline__ uint32_t smem_u32(const void* p) {
    uint32_t a;
    asm("{ .reg .u64 t; cvta.to.shared.u64 t, %1; cvt.u32.u64 %0, t; }" : "=r"(a) : "l"(p));
    return a;
}
__device__ __forceinline__ void cp16(uint32_t d, const void* g) {
    uint64_t ga;
    asm("cvta.to.global.u64 %0, %1;" : "=l"(ga) : "l"(g));
    asm volatile("cp.async.cg.shared.global [%0], [%1], 16;" :: "r"(d), "l"(ga) : "memory");
}
#define CP_COMMIT() asm volatile("cp.async.commit_group;" ::: "memory")
#define CP_WAIT(n)  asm volatile("cp.async.wait_group %0;" :: "n"(n) : "memory")

__device__ __forceinline__ void ldsm4(uint32_t a, uint32_t* r) {
    asm volatile("ldmatrix.sync.aligned.m8n8.x4.shared.b16 {%0,%1,%2,%3}, [%4];"
        : "=r"(r[0]), "=r"(r[1]), "=r"(r[2]), "=r"(r[3]) : "r"(a));
}
__device__ __forceinline__ void mma16816(float* d, const uint32_t* a, uint32_t b0, uint32_t b1) {
    asm volatile("mma.sync.aligned.m16n8k16.row.col.f32.f16.f16.f32 "
        "{%0,%1,%2,%3}, {%4,%5,%6,%7}, {%8,%9}, {%0,%1,%2,%3};"
        : "+f"(d[0]), "+f"(d[1]), "+f"(d[2]), "+f"(d[3])
        : "r"(a[0]), "r"(a[1]), "r"(a[2]), "r"(a[3]), "r"(b0), "r"(b1));
}

// ---------------- async tile loaders ----------------
// K tile: 64 rows(t) x 128 halves(ch), row stride LDKB
__device__ __forceinline__ void cp_ktile(uint32_t dst, const __half* src) {
    const int tid = threadIdx.x;
    #pragma unroll
    for (int j = 0; j < 4; j++) {
        int c = tid + j * 256;
        int row = c >> 4, cc = c & 15;
        cp16(dst + row * LDKB + cc * 16, src + row * DH + cc * 8);
    }
}
// V tile: 128 rows(dv) x 64 halves(t), row stride LDVB, src row stride TT
__device__ __forceinline__ void cp_vtile(uint32_t dst, const __half* src) {
    const int tid = threadIdx.x;
    #pragma unroll
    for (int j = 0; j < 4; j++) {
        int c = tid + j * 256;
        int row = c >> 3, cc = c & 7;
        cp16(dst + row * LDVB + cc * 16, src + (size_t)row * TT + cc * 8);
    }
}

// ---------------- prep: normalize Q,K; convert V to fp16 ----------------
__global__ __launch_bounds__(256) void prep_kernel(const float* __restrict__ q,
                                                   const float* __restrict__ k,
                                                   const float* __restrict__ v) {
    __shared__ float part[256];
    const int tid = threadIdx.x;
    const int t = tid & 63, g = tid >> 6;
    const int t0 = blockIdx.x * 64, bh = blockIdx.y, z = blockIdx.z;

    const float* src = (z == 0 ? q : (z == 1 ? k : v)) + (size_t)bh * DH * TT + t0 + t;
    float vals[32];
    #pragma unroll
    for (int i = 0; i < 32; i++) vals[i] = src[(size_t)(g * 32 + i) * TT];

    if (z < 2) {
        float ss = 0.f;
        #pragma unroll
        for (int i = 0; i < 32; i++) ss += vals[i] * vals[i];
        part[tid] = ss;
        __syncthreads();
        if (tid < 64)
            part[tid] = 1.0f / fmaxf(sqrtf(part[tid] + part[tid + 64] + part[tid + 128] + part[tid + 192]), 1e-12f);
        __syncthreads();
        float inv = part[t];
        __half2* dst = reinterpret_cast<__half2*>(
            (z == 0 ? g_QT : g_KT) + ((size_t)bh * TT + t0 + t) * DH + g * 32);
        #pragma unroll
        for (int i = 0; i < 16; i++)
            dst[i] = __floats2half2_rn(vals[2 * i] * inv, vals[2 * i + 1] * inv);
    } else {
        #pragma unroll
        for (int i = 0; i < 32; i++)
            g_VB[((size_t)bh * DH + g * 32 + i) * TT + t0 + t] = __float2half(vals[i]);
    }
}

// ---------------- main attention kernel ----------------
__global__ __launch_bounds__(256, 1) void attn_main(float* __restrict__ out) {
    extern __shared__ char smem[];
    const int tid = threadIdx.x;
    const int lane = tid & 31;
    const int wr = tid >> 5;          // warp id: q rows [wr*16, wr*16+16)
    const int q0 = blockIdx.x * QT;
    const int bh = blockIdx.y;
    const uint32_t sb = smem_u32(smem);

    const __half* gq = g_QT + ((size_t)bh * TT + q0) * DH;
    const __half* gk = g_KT + (size_t)bh * TT * DH;
    const __half* gv = g_VB + (size_t)bh * DH * TT;

    // ---- stage Q tile (128 x 128 halves, row stride LDKB) and load A frags ----
    {
        #pragma unroll
        for (int j = 0; j < 8; j++) {
            int c = tid + j * 256;
            int row = c >> 4, cc = c & 15;
            cp16(sb + OFF_K0 + row * LDKB + cc * 16, gq + row * DH + cc * 8);
        }
        CP_COMMIT();
        CP_WAIT(0);
        __syncthreads();
    }
    uint32_t qA[8][4];
    {
        const uint32_t arow = ((lane >> 3) & 1) * 8 + (lane & 7);
        const uint32_t acol = ((lane >> 4) & 1) * 8;
        const uint32_t qb = sb + OFF_K0 + (wr * 16 + arow) * LDKB + acol * 2;
        #pragma unroll
        for (int c = 0; c < 8; c++) ldsm4(qb + c * 32, qA[c]);
    }
    __syncthreads();   // done reading Q staging before K/V prefetch overwrites it

    // ---- prefetch first two K/V tiles ----
    cp_ktile(sb + OFF_K0, gk);
    cp_vtile(sb + OFF_V0, gv);
    CP_COMMIT();
    cp_ktile(sb + OFF_K1, gk + (size_t)KT * DH);
    cp_vtile(sb + OFF_V1, gv + KT);
    CP_COMMIT();

    float oacc[16][4];
    #pragma unroll
    for (int j = 0; j < 16; j++) {
        oacc[j][0] = oacc[j][1] = oacc[j][2] = oacc[j][3] = 0.f;
    }
    float lsum0 = 0.f, lsum1 = 0.f;

    const uint32_t brow = ((lane >> 4) & 1) * 8 + (lane & 7);   // ldmatrix row-in-tile
    const uint32_t bcol = ((lane >> 3) & 1) * 8;                // ldmatrix col-8 select

    for (int i = 0; i < NITER; i++) {
        if (i + 1 < NITER) { CP_WAIT(1); } else { CP_WAIT(0); }
        __syncthreads();
        const uint32_t ks = sb + ((i & 1) ? OFF_K1 : OFF_K0);
        const uint32_t vs = sb + ((i & 1) ? OFF_V1 : OFF_V0);

        // ---- S = Qn . Kn^T  (16q x 64k per warp, registers) ----
        float sacc[8][4];
        #pragma unroll
        for (int j = 0; j < 8; j++)
            sacc[j][0] = sacc[j][1] = sacc[j][2] = sacc[j][3] = 0.f;
        #pragma unroll
        for (int c = 0; c < 8; c++) {
            #pragma unroll
            for (int j = 0; j < 4; j++) {
                uint32_t b[4];
                ldsm4(ks + (j * 16 + brow) * LDKB + (c * 16 + bcol) * 2, b);
                mma16816(sacc[j * 2],     qA[c], b[0], b[1]);
                mma16816(sacc[j * 2 + 1], qA[c], b[2], b[3]);
            }
        }

        // ---- P = exp(alpha*S) in registers; repack C-frags -> A-frags ----
        uint32_t p[4][4];
        #pragma unroll
        for (int jj = 0; jj < 8; jj++) {
            float e0 = __expf(ALPHA * sacc[jj][0]);
            float e1 = __expf(ALPHA * sacc[jj][1]);
            float e2 = __expf(ALPHA * sacc[jj][2]);
            float e3 = __expf(ALPHA * sacc[jj][3]);
            lsum0 += e0 + e1;
            lsum1 += e2 + e3;
            __half2 h01 = __floats2half2_rn(e0, e1);
            __half2 h23 = __floats2half2_rn(e2, e3);
            p[jj >> 1][(jj & 1) * 2]     = *reinterpret_cast<uint32_t*>(&h01);
            p[jj >> 1][(jj & 1) * 2 + 1] = *reinterpret_cast<uint32_t*>(&h23);
        }

        // ---- O += P . V^T  (16q x 128dv per warp) ----
        #pragma unroll
        for (int kc = 0; kc < 4; kc++) {
            #pragma unroll
            for (int j = 0; j < 8; j++) {
                uint32_t b[4];
                ldsm4(vs + (j * 16 + brow) * LDVB + (kc * 16 + bcol) * 2, b);
                mma16816(oacc[j * 2],     p[kc], b[0], b[1]);
                mma16816(oacc[j * 2 + 1], p[kc], b[2], b[3]);
            }
        }

        __syncthreads();   // all warps done with this buffer
        if (i + 2 < NITER) {
            const uint32_t kd = sb + ((i & 1) ? OFF_K1 : OFF_K0);
            const uint32_t vd = sb + ((i & 1) ? OFF_V1 : OFF_V0);
            cp_ktile(kd, gk + (size_t)(i + 2) * KT * DH);
            cp_vtile(vd, gv + (size_t)(i + 2) * KT);
            CP_COMMIT();
        }
    }

    // ---- epilogue: O regs -> smem [q][dv], rowsum -> smem, scaled write ----
    float* Osf = reinterpret_cast<float*>(smem + OFF_K0);
    float* lsf = reinterpret_cast<float*>(smem + OFF_LS);
    const int r2 = lane >> 2, tg = lane & 3;
    #pragma unroll
    for (int jj = 0; jj < 16; jj++) {
        float2 v01 = make_float2(oacc[jj][0], oacc[jj][1]);
        float2 v23 = make_float2(oacc[jj][2], oacc[jj][3]);
        *reinterpret_cast<float2*>(&Osf[(wr * 16 + r2) * LDO + jj * 8 + tg * 2]) = v01;
        *reinterpret_cast<float2*>(&Osf[(wr * 16 + r2 + 8) * LDO + jj * 8 + tg * 2]) = v23;
    }
    float t0 = lsum0 + __shfl_xor_sync(0xffffffffu, lsum0, 1);
    t0 += __shfl_xor_sync(0xffffffffu, t0, 2);
    float t1 = lsum1 + __shfl_xor_sync(0xffffffffu, lsum1, 1);
    t1 += __shfl_xor_sync(0xffffffffu, t1, 2);
    if (tg == 0) {
        lsf[wr * 16 + r2] = t0;
        lsf[wr * 16 + r2 + 8] = t1;
    }
    __syncthreads();
    if (tid < 128) lsf[tid] = 1.0f / lsf[tid];
    __syncthreads();

    float* ob = out + (size_t)bh * DH * TT + q0;
    #pragma unroll
    for (int dvi = 0; dvi < 16; dvi++) {
        const int dv = wr * 16 + dvi;
        #pragma unroll
        for (int s = 0; s < 4; s++) {
            const int qq = lane + s * 32;
            ob[(size_t)dv * TT + qq] = Osf[qq * LDO + dv] * lsf[qq];
        }
    }
}

extern "C" void kernel_launch(void* const* d_in, const int* in_sizes, int n_in,
                              void* d_out, int out_size) {
    const float* q = (const float*)d_in[0];
    const float* k = (const float*)d_in[1];
    const float* v = (const float*)d_in[2];
    float* out = (float*)d_out;

    cudaFuncSetAttribute(attn_main, cudaFuncAttributeMaxDynamicSharedMemorySize, SMEM_BYTES);

    prep_kernel<<<dim3(TT / 64, NBH, 3), 256>>>(q, k, v);
    attn_main<<<dim3(TT / QT, NBH), 256, SMEM_BYTES>>>(out);
}